// round 1
// baseline (speedup 1.0000x reference)
#include <cuda_runtime.h>
#include <math.h>

// Model dims
#define BB 64
#define SS 128
#define FF 16
#define HH 64
// d_out layout: [ output(64*2) | wd_attn(16*64*128*128) | rd_attn(same) ]
#define ATTN_ELEMS (16u*64u*128u*128u)

// Scratch (allocation-free rule: __device__ globals)
__device__ float g_lstm[2ull*BB*FF*SS*HH];   // [br][b][f][s][h]  (67 MB)
__device__ float g_pooled[2ull*BB*FF*HH];    // [br][b][f][h]

__device__ __forceinline__ float sigf(float x){ return 1.f/(1.f+expf(-x)); }

// ---------------------------------------------------------------------------
// LSTM: one block per (branch, b, f). 256 threads; thread g owns gate row g.
// Whh row (64 floats) lives in registers; h lives in shared.
// ---------------------------------------------------------------------------
__global__ __launch_bounds__(256) void lstm_kernel(
    const float* __restrict__ wd_x, const float* __restrict__ rd_x,
    const float* __restrict__ wd_Wih, const float* __restrict__ wd_Whh,
    const float* __restrict__ wd_bih, const float* __restrict__ wd_bhh,
    const float* __restrict__ rd_Wih, const float* __restrict__ rd_Whh,
    const float* __restrict__ rd_bih, const float* __restrict__ rd_bhh)
{
    int idx = blockIdx.x;
    int br = idx >> 10;
    int b  = (idx >> 4) & 63;
    int f  = idx & 15;
    const float* x   = br ? rd_x   : wd_x;
    const float* Wih = br ? rd_Wih : wd_Wih;
    const float* Whh = br ? rd_Whh : wd_Whh;
    const float* bih = br ? rd_bih : wd_bih;
    const float* bhh = br ? rd_bhh : wd_bhh;
    int g = threadIdx.x;

    __shared__ float sh_h[64];
    __shared__ float sh_x[128];
    __shared__ float sh_g[256];

    float wrow[64];
    const float4* wr4 = (const float4*)(Whh + ((size_t)f*256 + g)*64);
    #pragma unroll
    for (int j = 0; j < 16; j++) {
        float4 v = wr4[j];
        wrow[4*j+0]=v.x; wrow[4*j+1]=v.y; wrow[4*j+2]=v.z; wrow[4*j+3]=v.w;
    }
    float wih  = Wih[f*256+g];
    float bias = bih[f*256+g] + bhh[f*256+g];
    if (g < 128) sh_x[g] = x[((size_t)b*128 + g)*16 + f];
    if (g < 64)  sh_h[g] = 0.f;
    float c = 0.f;
    float* outp = g_lstm + (((size_t)br*BB + b)*FF + f)*(size_t)(SS*HH);
    __syncthreads();

    for (int s = 0; s < 128; s++) {
        float a0=0.f,a1=0.f,a2=0.f,a3=0.f;
        #pragma unroll
        for (int j = 0; j < 64; j += 4) {
            a0 += wrow[j+0]*sh_h[j+0];
            a1 += wrow[j+1]*sh_h[j+1];
            a2 += wrow[j+2]*sh_h[j+2];
            a3 += wrow[j+3]*sh_h[j+3];
        }
        sh_g[g] = sh_x[s]*wih + bias + ((a0+a1)+(a2+a3));
        __syncthreads();
        if (g < 64) {
            float ig = sigf(sh_g[g]);
            float fg = sigf(sh_g[64+g]);
            float gg = tanhf(sh_g[128+g]);
            float og = sigf(sh_g[192+g]);
            c = fg*c + ig*gg;
            float h = og*tanhf(c);
            sh_h[g] = h;
            outp[s*64+g] = h;
        }
        __syncthreads();
    }
}

// ---------------------------------------------------------------------------
// Attention: one block per (branch, b, f). 128 threads; thread t = query row t.
// Smem: K/V (stride 68 for float4 broadcast reads), two score buffers
// (stride 129: conflict-free row & column access). ~204 KB dynamic smem.
// ---------------------------------------------------------------------------
#define KV_STRIDE 68
#define SB_STRIDE 129
#define ATTN_SMEM_FLOATS (128*KV_STRIDE*2 + 128*SB_STRIDE*2 + 192 + 64 + 256)
#define ATTN_SMEM_BYTES  (ATTN_SMEM_FLOATS*4)

__global__ __launch_bounds__(128) void attn_kernel(
    const float* __restrict__ wd_aw, const float* __restrict__ wd_ab,
    const float* __restrict__ wd_ow, const float* __restrict__ wd_ob,
    const float* __restrict__ rd_aw, const float* __restrict__ rd_ab,
    const float* __restrict__ rd_ow, const float* __restrict__ rd_ob,
    float* __restrict__ out_base)
{
    extern __shared__ float sm[];
    float* Ksm   = sm;                         // 128*68
    float* Vsm   = Ksm + 128*KV_STRIDE;        // 128*68
    float* Sb0   = Vsm + 128*KV_STRIDE;        // 128*129
    float* Sb1   = Sb0 + 128*SB_STRIDE;        // 128*129
    float* binsm = Sb1 + 128*SB_STRIDE;        // 192
    float* boutsm= binsm + 192;                // 64
    float* red   = boutsm + 64;                // 4*64
    float* Wsm   = Sb0;   // alias: QKV weights (12288 floats) during phase A
    float* Wosm  = Sb0;   // alias: out-proj weights (4096 floats) during phase C

    int idx = blockIdx.x;
    int br = idx >> 10;
    int b  = (idx >> 4) & 63;
    int f  = idx & 15;
    int t  = threadIdx.x;
    const float* aw = (br ? rd_aw : wd_aw) + (size_t)f*192*64;
    const float* ab = (br ? rd_ab : wd_ab) + f*192;
    const float* ow = (br ? rd_ow : wd_ow) + (size_t)f*64*64;
    const float* ob = (br ? rd_ob : wd_ob) + f*64;

    // stage QKV weights + bias
    for (int i = t; i < 3072; i += 128) ((float4*)Wsm)[i] = ((const float4*)aw)[i];
    for (int i = t; i < 192;  i += 128) binsm[i] = ab[i];

    // my LSTM row (S-position t)
    float xr[64];
    {
        const float4* X4 = (const float4*)(g_lstm +
            (((size_t)br*BB + b)*FF + f)*(size_t)(SS*HH) + (size_t)t*64);
        #pragma unroll
        for (int j = 0; j < 16; j++) {
            float4 v = X4[j];
            xr[4*j]=v.x; xr[4*j+1]=v.y; xr[4*j+2]=v.z; xr[4*j+3]=v.w;
        }
    }
    __syncthreads();

    // Phase A: K and V rows -> smem
    for (int g2 = 0; g2 < 64; g2++) {
        float ak = binsm[64+g2], av = binsm[128+g2];
        const float4* wk = (const float4*)(Wsm + (64+g2)*64);
        const float4* wv = (const float4*)(Wsm + (128+g2)*64);
        #pragma unroll
        for (int j = 0; j < 16; j++) {
            float4 a = wk[j]; float4 cc = wv[j];
            ak += a.x*xr[4*j] + a.y*xr[4*j+1] + a.z*xr[4*j+2] + a.w*xr[4*j+3];
            av += cc.x*xr[4*j] + cc.y*xr[4*j+1] + cc.z*xr[4*j+2] + cc.w*xr[4*j+3];
        }
        Ksm[t*KV_STRIDE+g2] = ak;
        Vsm[t*KV_STRIDE+g2] = av;
    }
    // q stays in registers (fully unrolled so indices are static)
    float q[64];
    #pragma unroll
    for (int g2 = 0; g2 < 64; g2++) {
        float aq = binsm[g2];
        const float4* wq = (const float4*)(Wsm + g2*64);
        #pragma unroll
        for (int j = 0; j < 16; j++) {
            float4 a = wq[j];
            aq += a.x*xr[4*j] + a.y*xr[4*j+1] + a.z*xr[4*j+2] + a.w*xr[4*j+3];
        }
        q[g2] = aq;
    }
    __syncthreads();   // everyone done with Wsm + K/V complete

    // Phase B: scores (both heads), softmax, store weights in Sb0/Sb1
    const float scale = 0.1767766952966369f; // 1/sqrt(32)
    for (int k = 0; k < 128; k++) {
        const float4* Kr = (const float4*)(Ksm + k*KV_STRIDE);
        float s0=0.f, s1v=0.f;
        #pragma unroll
        for (int j = 0; j < 8; j++) {
            float4 a = Kr[j];       // head 0 channels
            float4 c4 = Kr[8+j];    // head 1 channels
            s0  += a.x*q[4*j]    + a.y*q[4*j+1]    + a.z*q[4*j+2]    + a.w*q[4*j+3];
            s1v += c4.x*q[32+4*j]+ c4.y*q[32+4*j+1]+ c4.z*q[32+4*j+2]+ c4.w*q[32+4*j+3];
        }
        Sb0[t*SB_STRIDE+k] = s0*scale;
        Sb1[t*SB_STRIDE+k] = s1v*scale;
    }
    {
        float* row = Sb0 + t*SB_STRIDE;
        float m = -1e30f;
        for (int k=0;k<128;k++) m = fmaxf(m, row[k]);
        float s = 0.f;
        for (int k=0;k<128;k++){ float e = expf(row[k]-m); row[k]=e; s+=e; }
        float inv = 1.f/s;
        for (int k=0;k<128;k++) row[k]*=inv;
        row = Sb1 + t*SB_STRIDE;
        m = -1e30f;
        for (int k=0;k<128;k++) m = fmaxf(m, row[k]);
        s = 0.f;
        for (int k=0;k<128;k++){ float e = expf(row[k]-m); row[k]=e; s+=e; }
        inv = 1.f/s;
        for (int k=0;k<128;k++) row[k]*=inv;
    }
    __syncthreads();

    // head-averaged attention weights -> d_out (coalesced cooperative store)
    {
        float* outw = out_base + 128 + (size_t)br*ATTN_ELEMS + (((size_t)f*64 + b) << 14);
        for (int i = t; i < 16384; i += 128) {
            int r = i >> 7, c2 = i & 127;
            outw[i] = 0.5f*(Sb0[r*SB_STRIDE+c2] + Sb1[r*SB_STRIDE+c2]);
        }
    }

    // O = w @ V (per-head halves)
    float orow[64];
    #pragma unroll
    for (int d = 0; d < 64; d++) orow[d] = 0.f;
    for (int k = 0; k < 128; k++) {
        float w0 = Sb0[t*SB_STRIDE+k], w1 = Sb1[t*SB_STRIDE+k];
        const float4* Vr = (const float4*)(Vsm + k*KV_STRIDE);
        #pragma unroll
        for (int j = 0; j < 8; j++) {
            float4 a  = Vr[j];
            float4 c4 = Vr[8+j];
            orow[4*j]     += w0*a.x;  orow[4*j+1]   += w0*a.y;
            orow[4*j+2]   += w0*a.z;  orow[4*j+3]   += w0*a.w;
            orow[32+4*j]  += w1*c4.x; orow[32+4*j+1]+= w1*c4.y;
            orow[32+4*j+2]+= w1*c4.z; orow[32+4*j+3]+= w1*c4.w;
        }
    }
    __syncthreads();   // done reading Sb0 -> safe to overwrite with Wout

    for (int i = t; i < 1024; i += 128) ((float4*)Wosm)[i] = ((const float4*)ow)[i];
    if (t < 64) boutsm[t] = ob[t];
    __syncthreads();

    // Phase C: out-proj + mean over S (block reduction). bias folded in at the end.
    int lane = t & 31, warp = t >> 5;
    for (int o = 0; o < 64; o++) {
        float acc = 0.f;
        const float4* wr = (const float4*)(Wosm + o*64);
        #pragma unroll
        for (int j = 0; j < 16; j++) {
            float4 a = wr[j];
            acc += a.x*orow[4*j] + a.y*orow[4*j+1] + a.z*orow[4*j+2] + a.w*orow[4*j+3];
        }
        #pragma unroll
        for (int off = 16; off; off >>= 1)
            acc += __shfl_down_sync(0xffffffffu, acc, off);
        if (lane == 0) red[warp*64 + o] = acc;
    }
    __syncthreads();
    if (t < 64) {
        float s = red[t] + red[64+t] + red[128+t] + red[192+t];
        g_pooled[(((size_t)br*BB + b)*FF + f)*HH + t] = s*(1.f/128.f) + boutsm[t];
    }
}

// ---------------------------------------------------------------------------
// Head: static/time MLPs + final fc. One block, thread = batch row.
// ---------------------------------------------------------------------------
__global__ __launch_bounds__(64) void head_kernel(
    const float* __restrict__ stat, const float* __restrict__ tg,
    const float* __restrict__ d1w, const float* __restrict__ d1b,
    const float* __restrict__ d2w, const float* __restrict__ d2b,
    const float* __restrict__ t1w, const float* __restrict__ t1b,
    const float* __restrict__ t2w, const float* __restrict__ t2b,
    const float* __restrict__ fcw, const float* __restrict__ fcb,
    float* __restrict__ out)
{
    int b = threadIdx.x;
    float s1[64];
    #pragma unroll
    for (int j = 0; j < 64; j++) {
        float acc = d1b[j];
        #pragma unroll
        for (int k = 0; k < 32; k++) acc += stat[b*32+k]*d1w[j*32+k];
        s1[j] = fmaxf(acc, 0.f);
    }
    float s2[32];
    #pragma unroll
    for (int j = 0; j < 32; j++) {
        float acc = d2b[j];
        #pragma unroll
        for (int k = 0; k < 64; k++) acc += s1[k]*d2w[j*64+k];
        s2[j] = fmaxf(acc, 0.f);
    }
    float tv = tg[b];
    float tt1[16];
    #pragma unroll
    for (int j = 0; j < 16; j++) tt1[j] = fmaxf(t1b[j] + tv*t1w[j], 0.f);
    float tt2[8];
    #pragma unroll
    for (int j = 0; j < 8; j++) {
        float acc = t2b[j];
        #pragma unroll
        for (int k = 0; k < 16; k++) acc += tt1[k]*t2w[j*16+k];
        tt2[j] = fmaxf(acc, 0.f);
    }
    const float* p_wd = g_pooled + (size_t)b*1024;
    const float* p_rd = g_pooled + 65536u + (size_t)b*1024;
    #pragma unroll
    for (int o = 0; o < 2; o++) {
        const float* w = fcw + o*2088;
        float acc = fcb[o];
        for (int i = 0; i < 1024; i++) acc += p_wd[i]*w[i];
        for (int i = 0; i < 1024; i++) acc += p_rd[i]*w[1024+i];
        #pragma unroll
        for (int k = 0; k < 32; k++) acc += s2[k]*w[2048+k];
        #pragma unroll
        for (int k = 0; k < 8; k++)  acc += tt2[k]*w[2080+k];
        out[b*2+o] = acc;
    }
}

// ---------------------------------------------------------------------------
extern "C" void kernel_launch(void* const* d_in, const int* in_sizes, int n_in,
                              void* d_out, int out_size)
{
    const float* wd_x   = (const float*)d_in[0];
    const float* rd_x   = (const float*)d_in[1];
    const float* stat   = (const float*)d_in[2];
    const float* tg     = (const float*)d_in[3];
    const float* wd_Wih = (const float*)d_in[4];
    const float* wd_Whh = (const float*)d_in[5];
    const float* wd_bih = (const float*)d_in[6];
    const float* wd_bhh = (const float*)d_in[7];
    const float* rd_Wih = (const float*)d_in[8];
    const float* rd_Whh = (const float*)d_in[9];
    const float* rd_bih = (const float*)d_in[10];
    const float* rd_bhh = (const float*)d_in[11];
    const float* wd_aw  = (const float*)d_in[12];
    const float* wd_ab  = (const float*)d_in[13];
    const float* wd_ow  = (const float*)d_in[14];
    const float* wd_ob  = (const float*)d_in[15];
    const float* rd_aw  = (const float*)d_in[16];
    const float* rd_ab  = (const float*)d_in[17];
    const float* rd_ow  = (const float*)d_in[18];
    const float* rd_ob  = (const float*)d_in[19];
    const float* d1w = (const float*)d_in[20];
    const float* d1b = (const float*)d_in[21];
    const float* d2w = (const float*)d_in[22];
    const float* d2b = (const float*)d_in[23];
    const float* t1w = (const float*)d_in[24];
    const float* t1b = (const float*)d_in[25];
    const float* t2w = (const float*)d_in[26];
    const float* t2b = (const float*)d_in[27];
    const float* fcw = (const float*)d_in[28];
    const float* fcb = (const float*)d_in[29];
    float* out = (float*)d_out;

    cudaFuncSetAttribute(attn_kernel,
                         cudaFuncAttributeMaxDynamicSharedMemorySize,
                         ATTN_SMEM_BYTES);

    lstm_kernel<<<2048, 256>>>(wd_x, rd_x, wd_Wih, wd_Whh, wd_bih, wd_bhh,
                               rd_Wih, rd_Whh, rd_bih, rd_bhh);
    attn_kernel<<<2048, 128, ATTN_SMEM_BYTES>>>(wd_aw, wd_ab, wd_ow, wd_ob,
                                                rd_aw, rd_ab, rd_ow, rd_ob, out);
    head_kernel<<<1, 64>>>(stat, tg, d1w, d1b, d2w, d2b,
                           t1w, t1b, t2w, t2b, fcw, fcb, out);
}

// round 2
// speedup vs baseline: 1.0883x; 1.0883x over previous
#include <cuda_runtime.h>
#include <math.h>

// Model dims
#define BB 64
#define SS 128
#define FF 16
#define HH 64
#define ATTN_ELEMS (16u*64u*128u*128u)

typedef unsigned long long u64;

// Scratch (allocation-free rule: __device__ globals)
__device__ float g_lstm[2ull*BB*FF*SS*HH];   // [br][b][f][s][h]  (67 MB)
__device__ float g_pooled[2ull*BB*FF*HH];    // [br][b][f][h]

// ---- packed f32x2 helpers (PTX-only FFMA2 path) ----
__device__ __forceinline__ u64 pk2(float lo, float hi){
    u64 r; asm("mov.b64 %0, {%1, %2};" : "=l"(r) : "f"(lo), "f"(hi)); return r;
}
__device__ __forceinline__ void upk2(u64 v, float& lo, float& hi){
    asm("mov.b64 {%0, %1}, %2;" : "=f"(lo), "=f"(hi) : "l"(v));
}
__device__ __forceinline__ u64 ffma2(u64 a, u64 b, u64 c){
    u64 d; asm("fma.rn.f32x2 %0, %1, %2, %3;" : "=l"(d) : "l"(a), "l"(b), "l"(c)); return d;
}
__device__ __forceinline__ u64 fadd2(u64 a, u64 b){
    u64 d; asm("add.rn.f32x2 %0, %1, %2;" : "=l"(d) : "l"(a), "l"(b)); return d;
}
__device__ __forceinline__ u64 fmul2(u64 a, u64 b){
    u64 d; asm("mul.rn.f32x2 %0, %1, %2;" : "=l"(d) : "l"(a), "l"(b)); return d;
}
__device__ __forceinline__ float hsum2(u64 v){ float lo,hi; upk2(v,lo,hi); return lo+hi; }

__device__ __forceinline__ float sigf(float x){ return 1.f/(1.f+__expf(-x)); }
__device__ __forceinline__ float tanhfast(float x){ return 2.f/(1.f+__expf(-2.f*x)) - 1.f; }

// 64-float dot: w (16B-aligned smem/any), xp = 32 packed u64 register operand
__device__ __forceinline__ float dot64p(const float* __restrict__ w, const u64* xp){
    const ulonglong2* W2 = (const ulonglong2*)w;
    u64 a0=0ull,a1=0ull,a2=0ull,a3=0ull;
    #pragma unroll
    for (int j = 0; j < 8; j++) {
        ulonglong2 w0 = W2[2*j];
        ulonglong2 w1 = W2[2*j+1];
        a0 = ffma2(w0.x, xp[4*j+0], a0);
        a1 = ffma2(w0.y, xp[4*j+1], a1);
        a2 = ffma2(w1.x, xp[4*j+2], a2);
        a3 = ffma2(w1.y, xp[4*j+3], a3);
    }
    return hsum2(fadd2(fadd2(a0,a1),fadd2(a2,a3)));
}

// ---------------------------------------------------------------------------
// LSTM: one block per (branch, b, f). 256 threads; thread g owns gate row g.
// Whh row lives packed in registers; h in shared, read as 128-bit.
// ---------------------------------------------------------------------------
__global__ __launch_bounds__(256,2) void lstm_kernel(
    const float* __restrict__ wd_x, const float* __restrict__ rd_x,
    const float* __restrict__ wd_Wih, const float* __restrict__ wd_Whh,
    const float* __restrict__ wd_bih, const float* __restrict__ wd_bhh,
    const float* __restrict__ rd_Wih, const float* __restrict__ rd_Whh,
    const float* __restrict__ rd_bih, const float* __restrict__ rd_bhh)
{
    int idx = blockIdx.x;
    int br = idx >> 10;
    int b  = (idx >> 4) & 63;
    int f  = idx & 15;
    const float* x   = br ? rd_x   : wd_x;
    const float* Wih = br ? rd_Wih : wd_Wih;
    const float* Whh = br ? rd_Whh : wd_Whh;
    const float* bih = br ? rd_bih : wd_bih;
    const float* bhh = br ? rd_bhh : wd_bhh;
    int g = threadIdx.x;

    __shared__ __align__(16) float sh_h[64];
    __shared__ float sh_x[128];
    __shared__ float sh_g[256];

    u64 wp[32];
    {
        const float4* wr4 = (const float4*)(Whh + ((size_t)f*256 + g)*64);
        #pragma unroll
        for (int j = 0; j < 16; j++) {
            float4 v = wr4[j];
            wp[2*j]   = pk2(v.x, v.y);
            wp[2*j+1] = pk2(v.z, v.w);
        }
    }
    float wih  = Wih[f*256+g];
    float bias = bih[f*256+g] + bhh[f*256+g];
    if (g < 128) sh_x[g] = x[((size_t)b*128 + g)*16 + f];
    if (g < 64)  sh_h[g] = 0.f;
    float c = 0.f;
    float* outp = g_lstm + (((size_t)br*BB + b)*FF + f)*(size_t)(SS*HH);
    __syncthreads();

    for (int s = 0; s < 128; s++) {
        const ulonglong2* H2 = (const ulonglong2*)sh_h;
        u64 a0=0ull,a1=0ull,a2=0ull,a3=0ull;
        #pragma unroll
        for (int j = 0; j < 8; j++) {
            ulonglong2 h0 = H2[2*j];
            ulonglong2 h1 = H2[2*j+1];
            a0 = ffma2(wp[4*j+0], h0.x, a0);
            a1 = ffma2(wp[4*j+1], h0.y, a1);
            a2 = ffma2(wp[4*j+2], h1.x, a2);
            a3 = ffma2(wp[4*j+3], h1.y, a3);
        }
        float dot = hsum2(fadd2(fadd2(a0,a1),fadd2(a2,a3)));
        sh_g[g] = fmaf(sh_x[s], wih, bias) + dot;
        __syncthreads();
        if (g < 64) {
            float ig = sigf(sh_g[g]);
            float fg = sigf(sh_g[64+g]);
            float gg = tanhfast(sh_g[128+g]);
            float og = sigf(sh_g[192+g]);
            c = fg*c + ig*gg;
            float h = og*tanhfast(c);
            sh_h[g] = h;
            outp[s*64+g] = h;
        }
        __syncthreads();
    }
}

// ---------------------------------------------------------------------------
// Attention: one block per (branch, b, f). 128 threads; thread t = query row t.
// Two-pass softmax (no max-subtraction; scores are tiny), no score buffers.
// smem = K/V (stride 68) + 8KB weight chunk + 128x33 transpose tile ~ 96.8 KB
// -> 2 CTAs/SM.
// ---------------------------------------------------------------------------
#define KV_STRIDE 68
#define SM_K     0
#define SM_V     (128*KV_STRIDE)
#define SM_WBUF  (2*128*KV_STRIDE)            // 2048 floats
#define SM_WTR   (SM_WBUF + 2048)             // 128*33 = 4224 floats
#define SM_BIN   (SM_WTR + 128*33)            // 192
#define SM_BOUT  (SM_BIN + 192)               // 64
#define SM_RED   (SM_BOUT + 64)               // 256
#define ATTN_SMEM_FLOATS (SM_RED + 256)
#define ATTN_SMEM_BYTES  (ATTN_SMEM_FLOATS*4)

__global__ __launch_bounds__(128,2) void attn_kernel(
    const float* __restrict__ wd_aw, const float* __restrict__ wd_ab,
    const float* __restrict__ wd_ow, const float* __restrict__ wd_ob,
    const float* __restrict__ rd_aw, const float* __restrict__ rd_ab,
    const float* __restrict__ rd_ow, const float* __restrict__ rd_ob,
    float* __restrict__ out_base)
{
    extern __shared__ __align__(16) float sm[];
    float* Ksm   = sm + SM_K;
    float* Vsm   = sm + SM_V;
    float* Wbuf  = sm + SM_WBUF;
    float* wtr   = sm + SM_WTR;
    float* binsm = sm + SM_BIN;
    float* boutsm= sm + SM_BOUT;
    float* red   = sm + SM_RED;

    int idx = blockIdx.x;
    int br = idx >> 10;
    int b  = (idx >> 4) & 63;
    int f  = idx & 15;
    int t  = threadIdx.x;
    const float* aw = (br ? rd_aw : wd_aw) + (size_t)f*192*64;
    const float* ab = (br ? rd_ab : wd_ab) + f*192;
    const float* ow = (br ? rd_ow : wd_ow) + (size_t)f*64*64;
    const float* ob = (br ? rd_ob : wd_ob) + f*64;

    // biases
    for (int i = t; i < 192; i += 128) binsm[i] = ab[i];
    if (t < 64) boutsm[t] = ob[t];

    // my LSTM row (S-position t), packed
    u64 xp[32];
    {
        const ulonglong2* X2 = (const ulonglong2*)(g_lstm +
            (((size_t)br*BB + b)*FF + f)*(size_t)(SS*HH) + (size_t)t*64);
        #pragma unroll
        for (int j = 0; j < 16; j++) {
            ulonglong2 v = X2[j];
            xp[2*j] = v.x; xp[2*j+1] = v.y;
        }
    }

    // ---- Phase A: QKV projection in 32-row weight chunks ----
    // chunks: K rows (W 64..127), V rows (W 128..191), then q rows (W 0..63)
    #pragma unroll 1
    for (int c = 0; c < 2; c++) {            // K
        __syncthreads();
        const float4* src = (const float4*)(aw + (size_t)(64 + 32*c)*64);
        for (int i = t; i < 512; i += 128) ((float4*)Wbuf)[i] = src[i];
        __syncthreads();
        #pragma unroll 1
        for (int r = 0; r < 32; r++) {
            float v = dot64p(Wbuf + r*64, xp) + binsm[64 + 32*c + r];
            Ksm[t*KV_STRIDE + 32*c + r] = v;
        }
    }
    #pragma unroll 1
    for (int c = 0; c < 2; c++) {            // V
        __syncthreads();
        const float4* src = (const float4*)(aw + (size_t)(128 + 32*c)*64);
        for (int i = t; i < 512; i += 128) ((float4*)Wbuf)[i] = src[i];
        __syncthreads();
        #pragma unroll 1
        for (int r = 0; r < 32; r++) {
            float v = dot64p(Wbuf + r*64, xp) + binsm[128 + 32*c + r];
            Vsm[t*KV_STRIDE + 32*c + r] = v;
        }
    }
    u64 qp[32];
    #pragma unroll 1
    for (int c = 0; c < 2; c++) {            // q (kept packed in regs)
        __syncthreads();
        const float4* src = (const float4*)(aw + (size_t)(32*c)*64);
        for (int i = t; i < 512; i += 128) ((float4*)Wbuf)[i] = src[i];
        __syncthreads();
        if (c == 0) {
            #pragma unroll
            for (int i = 0; i < 16; i++) {
                float d0 = dot64p(Wbuf + (2*i)*64,   xp) + binsm[2*i];
                float d1 = dot64p(Wbuf + (2*i+1)*64, xp) + binsm[2*i+1];
                qp[i] = pk2(d0, d1);
            }
        } else {
            #pragma unroll
            for (int i = 0; i < 16; i++) {
                float d0 = dot64p(Wbuf + (2*i)*64,   xp) + binsm[32+2*i];
                float d1 = dot64p(Wbuf + (2*i+1)*64, xp) + binsm[32+2*i+1];
                qp[16+i] = pk2(d0, d1);
            }
        }
    }
    // K/V writes (per-thread rows) all precede the q-chunk barriers, so they
    // are visible now.

    const float scale = 0.1767766952966369f; // 1/sqrt(32)

    // ---- Pass 1: scores -> exp (no max-sub) -> unnormalized O + sums ----
    u64 op[32];
    #pragma unroll
    for (int j = 0; j < 32; j++) op[j] = 0ull;
    float sum0 = 0.f, sum1 = 0.f;
    #pragma unroll 1
    for (int k = 0; k < 128; k++) {
        const ulonglong2* Kr = (const ulonglong2*)(Ksm + k*KV_STRIDE);
        u64 b0=0ull,b1=0ull,c0=0ull,c1=0ull;
        #pragma unroll
        for (int j = 0; j < 8; j++) {
            ulonglong2 kv = Kr[j];
            b0 = ffma2(kv.x, qp[2*j],   b0);
            b1 = ffma2(kv.y, qp[2*j+1], b1);
        }
        #pragma unroll
        for (int j = 8; j < 16; j++) {
            ulonglong2 kv = Kr[j];
            c0 = ffma2(kv.x, qp[2*j],   c0);
            c1 = ffma2(kv.y, qp[2*j+1], c1);
        }
        float s0 = hsum2(fadd2(b0,b1)) * scale;
        float s1 = hsum2(fadd2(c0,c1)) * scale;
        float e0 = __expf(s0), e1 = __expf(s1);
        sum0 += e0; sum1 += e1;
        u64 w0 = pk2(e0,e0), w1 = pk2(e1,e1);
        const ulonglong2* Vr = (const ulonglong2*)(Vsm + k*KV_STRIDE);
        #pragma unroll
        for (int j = 0; j < 8; j++) {
            ulonglong2 vv = Vr[j];
            op[2*j]   = ffma2(w0, vv.x, op[2*j]);
            op[2*j+1] = ffma2(w0, vv.y, op[2*j+1]);
        }
        #pragma unroll
        for (int j = 8; j < 16; j++) {
            ulonglong2 vv = Vr[j];
            op[2*j]   = ffma2(w1, vv.x, op[2*j]);
            op[2*j+1] = ffma2(w1, vv.y, op[2*j+1]);
        }
    }
    float inv0 = 1.f/sum0, inv1 = 1.f/sum1;
    {
        u64 i0 = pk2(inv0, inv0), i1 = pk2(inv1, inv1);
        #pragma unroll
        for (int j = 0; j < 16; j++) op[j] = fmul2(op[j], i0);
        #pragma unroll
        for (int j = 16; j < 32; j++) op[j] = fmul2(op[j], i1);
    }

    // ---- Pass 2: recompute scores, write head-avg attn weights (coalesced
    //      via 128x33 transpose tile) ----
    float* outw = out_base + 128 + (size_t)br*ATTN_ELEMS + (((size_t)f*64 + b) << 14);
    #pragma unroll 1
    for (int kc = 0; kc < 4; kc++) {
        #pragma unroll 1
        for (int kk = 0; kk < 32; kk++) {
            int k = kc*32 + kk;
            const ulonglong2* Kr = (const ulonglong2*)(Ksm + k*KV_STRIDE);
            u64 b0=0ull,b1=0ull,c0=0ull,c1=0ull;
            #pragma unroll
            for (int j = 0; j < 8; j++) {
                ulonglong2 kv = Kr[j];
                b0 = ffma2(kv.x, qp[2*j],   b0);
                b1 = ffma2(kv.y, qp[2*j+1], b1);
            }
            #pragma unroll
            for (int j = 8; j < 16; j++) {
                ulonglong2 kv = Kr[j];
                c0 = ffma2(kv.x, qp[2*j],   c0);
                c1 = ffma2(kv.y, qp[2*j+1], c1);
            }
            float s0 = hsum2(fadd2(b0,b1)) * scale;
            float s1 = hsum2(fadd2(c0,c1)) * scale;
            wtr[t*33 + kk] = 0.5f*(__expf(s0)*inv0 + __expf(s1)*inv1);
        }
        __syncthreads();
        for (int i = t; i < 4096; i += 128) {
            int r = i >> 5, cc = i & 31;
            outw[r*128 + kc*32 + cc] = wtr[r*33 + cc];
        }
        __syncthreads();
    }

    // ---- Phase C: out-projection + mean over S. Stage Wout into Ksm (free). ----
    for (int i = t; i < 1024; i += 128) ((float4*)Ksm)[i] = ((const float4*)ow)[i];
    __syncthreads();
    int lane = t & 31, warp = t >> 5;
    #pragma unroll 1
    for (int o = 0; o < 64; o++) {
        float acc = dot64p(Ksm + o*64, op);
        #pragma unroll
        for (int off = 16; off; off >>= 1)
            acc += __shfl_down_sync(0xffffffffu, acc, off);
        if (lane == 0) red[warp*64 + o] = acc;
    }
    __syncthreads();
    if (t < 64) {
        float s = red[t] + red[64+t] + red[128+t] + red[192+t];
        g_pooled[(((size_t)br*BB + b)*FF + f)*HH + t] = s*(1.f/128.f) + boutsm[t];
    }
}

// ---------------------------------------------------------------------------
// Head: static/time MLPs + final fc. One block, thread = batch row.
// ---------------------------------------------------------------------------
__global__ __launch_bounds__(64) void head_kernel(
    const float* __restrict__ stat, const float* __restrict__ tg,
    const float* __restrict__ d1w, const float* __restrict__ d1b,
    const float* __restrict__ d2w, const float* __restrict__ d2b,
    const float* __restrict__ t1w, const float* __restrict__ t1b,
    const float* __restrict__ t2w, const float* __restrict__ t2b,
    const float* __restrict__ fcw, const float* __restrict__ fcb,
    float* __restrict__ out)
{
    int b = threadIdx.x;
    float s1[64];
    #pragma unroll
    for (int j = 0; j < 64; j++) {
        float acc = d1b[j];
        #pragma unroll
        for (int k = 0; k < 32; k++) acc += stat[b*32+k]*d1w[j*32+k];
        s1[j] = fmaxf(acc, 0.f);
    }
    float s2[32];
    #pragma unroll
    for (int j = 0; j < 32; j++) {
        float acc = d2b[j];
        #pragma unroll
        for (int k = 0; k < 64; k++) acc += s1[k]*d2w[j*64+k];
        s2[j] = fmaxf(acc, 0.f);
    }
    float tv = tg[b];
    float tt1[16];
    #pragma unroll
    for (int j = 0; j < 16; j++) tt1[j] = fmaxf(t1b[j] + tv*t1w[j], 0.f);
    float tt2[8];
    #pragma unroll
    for (int j = 0; j < 8; j++) {
        float acc = t2b[j];
        #pragma unroll
        for (int k = 0; k < 16; k++) acc += tt1[k]*t2w[j*16+k];
        tt2[j] = fmaxf(acc, 0.f);
    }
    const float* p_wd = g_pooled + (size_t)b*1024;
    const float* p_rd = g_pooled + 65536u + (size_t)b*1024;
    #pragma unroll
    for (int o = 0; o < 2; o++) {
        const float* w = fcw + o*2088;
        float acc = fcb[o];
        for (int i = 0; i < 1024; i++) acc += p_wd[i]*w[i];
        for (int i = 0; i < 1024; i++) acc += p_rd[i]*w[1024+i];
        #pragma unroll
        for (int k = 0; k < 32; k++) acc += s2[k]*w[2048+k];
        #pragma unroll
        for (int k = 0; k < 8; k++)  acc += tt2[k]*w[2080+k];
        out[b*2+o] = acc;
    }
}

// ---------------------------------------------------------------------------
extern "C" void kernel_launch(void* const* d_in, const int* in_sizes, int n_in,
                              void* d_out, int out_size)
{
    const float* wd_x   = (const float*)d_in[0];
    const float* rd_x   = (const float*)d_in[1];
    const float* stat   = (const float*)d_in[2];
    const float* tg     = (const float*)d_in[3];
    const float* wd_Wih = (const float*)d_in[4];
    const float* wd_Whh = (const float*)d_in[5];
    const float* wd_bih = (const float*)d_in[6];
    const float* wd_bhh = (const float*)d_in[7];
    const float* rd_Wih = (const float*)d_in[8];
    const float* rd_Whh = (const float*)d_in[9];
    const float* rd_bih = (const float*)d_in[10];
    const float* rd_bhh = (const float*)d_in[11];
    const float* wd_aw  = (const float*)d_in[12];
    const float* wd_ab  = (const float*)d_in[13];
    const float* wd_ow  = (const float*)d_in[14];
    const float* wd_ob  = (const float*)d_in[15];
    const float* rd_aw  = (const float*)d_in[16];
    const float* rd_ab  = (const float*)d_in[17];
    const float* rd_ow  = (const float*)d_in[18];
    const float* rd_ob  = (const float*)d_in[19];
    const float* d1w = (const float*)d_in[20];
    const float* d1b = (const float*)d_in[21];
    const float* d2w = (const float*)d_in[22];
    const float* d2b = (const float*)d_in[23];
    const float* t1w = (const float*)d_in[24];
    const float* t1b = (const float*)d_in[25];
    const float* t2w = (const float*)d_in[26];
    const float* t2b = (const float*)d_in[27];
    const float* fcw = (const float*)d_in[28];
    const float* fcb = (const float*)d_in[29];
    float* out = (float*)d_out;

    cudaFuncSetAttribute(attn_kernel,
                         cudaFuncAttributeMaxDynamicSharedMemorySize,
                         ATTN_SMEM_BYTES);

    lstm_kernel<<<2048, 256>>>(wd_x, rd_x, wd_Wih, wd_Whh, wd_bih, wd_bhh,
                               rd_Wih, rd_Whh, rd_bih, rd_bhh);
    attn_kernel<<<2048, 128, ATTN_SMEM_BYTES>>>(wd_aw, wd_ab, wd_ow, wd_ob,
                                                rd_aw, rd_ab, rd_ow, rd_ob, out);
    head_kernel<<<1, 64>>>(stat, tg, d1w, d1b, d2w, d2b,
                           t1w, t1b, t2w, t2b, fcw, fcb, out);
}